// round 16
// baseline (speedup 1.0000x reference)
#include <cuda_runtime.h>
#include <cuda_fp16.h>
#include <math.h>
#include <cstdint>

#define NB 64
#define ND 2048
#define NA 256
#define NR 64
#define NTOK (NB*NA)   // 16384 tokens

// ---------------- device scratch (allocation-free rule) ----------------
__device__ float g_scale[NB];
__device__ __align__(16) __half g_Qh[(size_t)NTOK*NR];   // token-major [tok][r]
__device__ __align__(16) __half g_Kh[(size_t)NTOK*NR];   // token-major [tok][r]
__device__ __align__(16) __half g_VhT[(size_t)NB*NR*NA]; // r-major [b][r][tok]
__device__ __align__(16) __half g_WH[9*4096];            // 0:Ao 1:Aq1 2:Ak1 3:Av1 4:Ao1 5:Aq5 6:Ak5 7:Av5 8:Ao5
// fp16 hi/lo split W for the layer-1 tensor GEMM
__device__ __align__(16) __half g_Whi[192*ND];
__device__ __align__(16) __half g_Wlo[192*ND];

// ---------------- PTX helpers ----------------
__device__ __forceinline__ uint32_t smem_u32(const void* p) {
    uint32_t a;
    asm("{ .reg .u64 t; cvta.to.shared.u64 t, %1; cvt.u32.u64 %0, t; }" : "=r"(a) : "l"(p));
    return a;
}
__device__ __forceinline__ void cp16(uint32_t d, const void* s) {
    asm volatile("cp.async.cg.shared.global [%0], [%1], 16;" :: "r"(d), "l"(s));
}
__device__ __forceinline__ void ldm4(uint32_t* r, uint32_t a) {
    asm volatile("ldmatrix.sync.aligned.m8n8.x4.shared.b16 {%0,%1,%2,%3}, [%4];"
        : "=r"(r[0]), "=r"(r[1]), "=r"(r[2]), "=r"(r[3]) : "r"(a));
}
__device__ __forceinline__ void mma16816(float* d, const uint32_t* a, uint32_t b0, uint32_t b1) {
    asm volatile("mma.sync.aligned.m16n8k16.row.col.f32.f16.f16.f32 "
        "{%0,%1,%2,%3}, {%4,%5,%6,%7}, {%8,%9}, {%0,%1,%2,%3};"
        : "+f"(d[0]), "+f"(d[1]), "+f"(d[2]), "+f"(d[3])
        : "r"(a[0]), "r"(a[1]), "r"(a[2]), "r"(a[3]), "r"(b0), "r"(b1));
}
__device__ __forceinline__ uint32_t pack2(float a, float b) {
    __half2 h = __floats2half2_rn(a, b);
    return *(uint32_t*)&h;
}

// ---------------- merged prep: small weights, per-batch scale, out zero, W hi/lo ------
__global__ void __launch_bounds__(256) k_misc(const float* __restrict__ L,
                       float* __restrict__ out,
                       const float* __restrict__ Aq, const float* __restrict__ Ak,
                       const float* __restrict__ Av,
                       const float* A0, const float* A1, const float* A2,
                       const float* A3, const float* A4, const float* A5,
                       const float* A6, const float* A7, const float* A8) {
    int blk = blockIdx.x;
    int tid = threadIdx.x;
    if (blk < 9) {
        const float* ptrs[9] = {A0, A1, A2, A3, A4, A5, A6, A7, A8};
        const float* src = ptrs[blk];
        __half* dst = g_WH + blk * 4096;
        for (int i = tid; i < 4096; i += 256) dst[i] = __float2half_rn(src[i]);
        return;
    }
    if (blk < 73) {
        int b = blk - 9;
        float c = (L[b * 2 * NA + tid] >= 1.0f) ? 1.0f : 0.0f;
        __shared__ float red[8];
        for (int o = 16; o > 0; o >>= 1) c += __shfl_down_sync(0xffffffffu, c, o);
        if ((tid & 31) == 0) red[tid >> 5] = c;
        __syncthreads();
        if (tid == 0) {
            float t = 0.f;
            #pragma unroll
            for (int i = 0; i < 8; i++) t += red[i];
            g_scale[b] = sqrtf(t + 1.0f);
        }
        return;
    }
    if (blk == 73) {
        if (tid < NB) out[tid] = 0.f;
        return;
    }
    // W hi/lo split: r = blk - 74 in 0..191
    int r = blk - 74;
    const float* src = (r < 64)  ? Aq + (size_t)r * ND
                     : (r < 128) ? Ak + (size_t)(r - 64) * ND
                                 : Av + (size_t)(r - 128) * ND;
    #pragma unroll
    for (int i = 0; i < 8; i++) {
        int k = tid + (i << 8);
        float a = src[k];
        __half h = __float2half_rn(a);
        __half l = __float2half_rn(a - __half2float(h));
        g_Whi[(size_t)r * ND + k] = h;
        g_Wlo[(size_t)r * ND + k] = l;
    }
}

// ---------------- fused layer-1 QKV GEMM with in-kernel x conversion (R9, locked) ----
#define ROWB    80
#define XH_ROW  384
#define XL_ROW  448
#define XF_OFF  40960u
#define XF_PITCH 272u
#define STAGE   49664u
#define GT_SMEM (2 * 49664)
__global__ void __launch_bounds__(256, 2) k_gemmTC(const float* __restrict__ x) {
    extern __shared__ __align__(16) char sm[];
    uint32_t smb = smem_u32(sm);
    int tid = threadIdx.x;
    int tok0 = blockIdx.x << 6;
    int bb_idx = tok0 >> 8;
    int n0 = tok0 & 255;
    int wid = tid >> 5, l = tid & 31;
    int mbase = (wid >> 1) * 48;
    int nbase = (wid & 1) << 5;

    float acc[3][4][4];
    #pragma unroll
    for (int mi = 0; mi < 3; mi++)
        #pragma unroll
        for (int nt = 0; nt < 4; nt++)
            #pragma unroll
            for (int e = 0; e < 4; e++) acc[mi][nt][e] = 0.f;

    uint32_t aOff = (uint32_t)((mbase + (l & 15)) * ROWB + ((l >> 4) << 4));
    uint32_t bOff = (uint32_t)((XH_ROW + nbase + (l & 7) + ((l >> 4) << 3)) * ROWB
                               + (((l >> 3) & 1) << 4));

    const float* xb = x + ((size_t)bb_idx * ND) * NA + n0;

    auto load_stage = [&](int c, int buf) {
        uint32_t bb = smb + (uint32_t)buf * STAGE;
        int k0 = c << 5;
        #pragma unroll
        for (int i = 0; i < 6; i++) {
            int s = tid + (i << 8);
            int row = s >> 2, u = s & 3;
            const __half* src = (row < 192)
                ? g_Whi + (size_t)row * ND + k0 + (u << 3)
                : g_Wlo + (size_t)(row - 192) * ND + k0 + (u << 3);
            cp16(bb + (uint32_t)(row * ROWB + (u << 4)), src);
        }
        #pragma unroll
        for (int i = 0; i < 2; i++) {
            int s = tid + (i << 8);
            int krow = s >> 4, u = s & 15;
            cp16(bb + XF_OFF + (uint32_t)(krow * XF_PITCH + (u << 4)),
                 xb + (size_t)(k0 + krow) * NA + (u << 2));
        }
        asm volatile("cp.async.commit_group;" ::: "memory");
    };

    int tq0 = tid & 15;
    int kq = (tid >> 4) << 1;

    load_stage(0, 0);
    for (int c = 0; c < 64; c++) {
        if (c < 63) {
            load_stage(c + 1, (c + 1) & 1);
            asm volatile("cp.async.wait_group 1;" ::: "memory");
        } else {
            asm volatile("cp.async.wait_group 0;" ::: "memory");
        }
        __syncthreads();
        char* bp = sm + (size_t)(c & 1) * STAGE;
        #pragma unroll
        for (int i = 0; i < 4; i++) {
            int tok = tq0 + (i << 4);
            float f0 = *(const float*)(bp + XF_OFF + kq * XF_PITCH + tok * 4);
            float f1 = *(const float*)(bp + XF_OFF + (kq + 1) * XF_PITCH + tok * 4);
            __half h0 = __float2half_rn(f0), h1 = __float2half_rn(f1);
            __half2 hh; hh.x = h0; hh.y = h1;
            *(uint32_t*)(bp + (XH_ROW + tok) * ROWB + kq * 2) = *(uint32_t*)&hh;
            *(uint32_t*)(bp + (XL_ROW + tok) * ROWB + kq * 2)
                = pack2(f0 - __half2float(h0), f1 - __half2float(h1));
        }
        __syncthreads();
        uint32_t bbu = smb + (uint32_t)(c & 1) * STAGE;
        uint32_t Ah = bbu + aOff;
        uint32_t Al = Ah + 192u * ROWB;
        uint32_t Bh = bbu + bOff;
        uint32_t Bl = Bh + 64u * ROWB;
        #pragma unroll
        for (int ks = 0; ks < 2; ks++) {
            uint32_t ko = (uint32_t)(ks << 5);
            uint32_t ah[3][4], al[3][4], bh[2][4], bl[2][4];
            #pragma unroll
            for (int mi = 0; mi < 3; mi++) {
                ldm4(ah[mi], Ah + (uint32_t)(mi * 16 * ROWB) + ko);
                ldm4(al[mi], Al + (uint32_t)(mi * 16 * ROWB) + ko);
            }
            #pragma unroll
            for (int nj = 0; nj < 2; nj++) {
                ldm4(bh[nj], Bh + (uint32_t)(nj * 16 * ROWB) + ko);
                ldm4(bl[nj], Bl + (uint32_t)(nj * 16 * ROWB) + ko);
            }
            #pragma unroll
            for (int mi = 0; mi < 3; mi++)
                #pragma unroll
                for (int nj = 0; nj < 2; nj++)
                    #pragma unroll
                    for (int h = 0; h < 2; h++) {
                        float* d = acc[mi][nj * 2 + h];
                        mma16816(d, ah[mi], bh[nj][2 * h], bh[nj][2 * h + 1]);
                        mma16816(d, ah[mi], bl[nj][2 * h], bl[nj][2 * h + 1]);
                        mma16816(d, al[mi], bh[nj][2 * h], bh[nj][2 * h + 1]);
                    }
        }
        __syncthreads();
    }

    float* S = (float*)sm;
    int lr = l >> 2, lc = (l & 3) << 1;
    #pragma unroll
    for (int mi = 0; mi < 3; mi++)
        #pragma unroll
        for (int nj = 0; nj < 2; nj++)
            #pragma unroll
            for (int h = 0; h < 2; h++) {
                int m = mbase + mi * 16 + lr;
                int n = nbase + nj * 16 + h * 8 + lc;
                float* d = acc[mi][nj * 2 + h];
                S[n * 196 + m]           = __frcp_rn(1.0f + __expf(-d[0]));
                S[(n + 1) * 196 + m]     = __frcp_rn(1.0f + __expf(-d[1]));
                S[n * 196 + m + 8]       = __frcp_rn(1.0f + __expf(-d[2]));
                S[(n + 1) * 196 + m + 8] = __frcp_rn(1.0f + __expf(-d[3]));
            }
    __syncthreads();
    #pragma unroll
    for (int i = 0; i < 4; i++) {
        int e = tid + (i << 8);
        int tok = e >> 4, q = e & 15;
        float4 vq = *(const float4*)(S + tok * 196 + (q << 2));
        float4 vk = *(const float4*)(S + tok * 196 + 64 + (q << 2));
        uint2 pq, pk;
        pq.x = pack2(vq.x, vq.y); pq.y = pack2(vq.z, vq.w);
        pk.x = pack2(vk.x, vk.y); pk.y = pack2(vk.z, vk.w);
        *(uint2*)(g_Qh + (size_t)(tok0 + tok) * NR + (q << 2)) = pq;
        *(uint2*)(g_Kh + (size_t)(tok0 + tok) * NR + (q << 2)) = pk;
    }
    {
        int r = tid >> 2, seg = tid & 3;
        __half* dst = g_VhT + ((size_t)bb_idx * NR + r) * NA + n0 + seg * 16;
        #pragma unroll
        for (int u = 0; u < 2; u++) {
            uint4 w;
            uint32_t* wp = (uint32_t*)&w;
            #pragma unroll
            for (int j2 = 0; j2 < 4; j2++) {
                int tk = seg * 16 + u * 8 + j2 * 2;
                wp[j2] = pack2(S[tk * 196 + 128 + r], S[(tk + 1) * 196 + 128 + r]);
            }
            *(uint4*)(dst + u * 8) = w;
        }
    }
}

// ---------------- FUSED attention + transition + QKV projections, 512 threads ---------
// Warp pair (wh, wh+8) owns 16 tokens; group = wid>>3 splits keys, then splits the
// projection tail by output columns. Last layer fuses the final quadratic reduction.
#define QS_OFF 0u
#define KS_OFF 18432u
#define VS_OFF 55296u
#define WS_OFF 89088u
#define RS_OFF 125952u
#define VT_OFF 0u
#define AT_SMEM 130048
__global__ void __launch_bounds__(512, 1) k_attn2(int wbase, int nw, int last,
                                                  const float* __restrict__ x,
                                                  float* __restrict__ out) {
    extern __shared__ __align__(16) char sm2[];
    uint32_t smb = smem_u32(sm2);
    int tid = threadIdx.x, wid = tid >> 5, l = tid & 31;
    int wh = wid & 7, grp = wid >> 3;
    int b = blockIdx.y;
    int halfsel = blockIdx.x;
    int tok0 = b * NA + halfsel * 128;

    // group A loads: Q + K
    #pragma unroll
    for (int i = 0; i < 2; i++) {
        int e = tid + (i << 9); int row = e >> 3, u = e & 7;
        cp16(smb + QS_OFF + row * 144 + u * 16, g_Qh + (size_t)(tok0 + row) * NR + u * 8);
    }
    #pragma unroll
    for (int i = 0; i < 4; i++) {
        int e = tid + (i << 9); int row = e >> 3, u = e & 7;
        cp16(smb + KS_OFF + row * 144 + u * 16, g_Kh + (size_t)(b * NA + row) * NR + u * 8);
    }
    asm volatile("cp.async.commit_group;" ::: "memory");
    // group B loads: V + W
    #pragma unroll
    for (int i = 0; i < 4; i++) {
        int e = tid + (i << 9); int r = e >> 5, u = e & 31;
        cp16(smb + VS_OFF + r * 528 + u * 16, g_VhT + ((size_t)b * NR + r) * NA + u * 8);
    }
    for (int wi = 0; wi < nw; wi++) {
        int row = tid >> 3, u = tid & 7;
        cp16(smb + WS_OFF + (uint32_t)wi * 9216 + row * 144 + u * 16,
             g_WH + (size_t)(wbase + wi) * 4096 + row * 64 + u * 8);
    }
    asm volatile("cp.async.commit_group;" ::: "memory");
    float invs = 1.0f / g_scale[b];
    asm volatile("cp.async.wait_group 1;" ::: "memory");
    __syncthreads();

    int n0 = wh << 4;
    uint32_t qa[4][4];
    uint32_t aQ = smb + QS_OFF + (uint32_t)((n0 + (l & 15)) * 144 + ((l >> 4) << 4));
    #pragma unroll
    for (int kc = 0; kc < 4; kc++) ldm4(qa[kc], aQ + kc * 32);

    float oacc[8][4];
    #pragma unroll
    for (int t = 0; t < 8; t++)
        #pragma unroll
        for (int e = 0; e < 4; e++) oacc[t][e] = 0.f;
    float rs_lo = 0.f, rs_hi = 0.f;

    uint32_t pa[4][4];
    // ---- kb=0: QK + exp (runs while V/W land) ----
    {
        float sacc[8][4];
        #pragma unroll
        for (int t = 0; t < 8; t++)
            #pragma unroll
            for (int e = 0; e < 4; e++) sacc[t][e] = 0.f;
        #pragma unroll
        for (int mg = 0; mg < 4; mg++) {
            uint32_t bK = smb + KS_OFF
                + (uint32_t)((grp * 128 + mg * 16 + (l & 7) + ((l >> 4) << 3)) * 144
                             + (((l >> 3) & 1) << 4));
            #pragma unroll
            for (int kc = 0; kc < 4; kc++) {
                uint32_t kbf[4];
                ldm4(kbf, bK + kc * 32);
                mma16816(sacc[mg * 2 + 0], qa[kc], kbf[0], kbf[1]);
                mma16816(sacc[mg * 2 + 1], qa[kc], kbf[2], kbf[3]);
            }
        }
        #pragma unroll
        for (int t = 0; t < 8; t++) {
            float p0 = __expf((sacc[t][0] - 64.0f) * invs);
            float p1 = __expf((sacc[t][1] - 64.0f) * invs);
            float p2 = __expf((sacc[t][2] - 64.0f) * invs);
            float p3 = __expf((sacc[t][3] - 64.0f) * invs);
            rs_lo += p0 + p1; rs_hi += p2 + p3;
            int j = t >> 1;
            if ((t & 1) == 0) { pa[j][0] = pack2(p0, p1); pa[j][1] = pack2(p2, p3); }
            else              { pa[j][2] = pack2(p0, p1); pa[j][3] = pack2(p2, p3); }
        }
    }
    asm volatile("cp.async.wait_group 0;" ::: "memory");
    __syncthreads();
    #pragma unroll
    for (int rg = 0; rg < 4; rg++) {
        uint32_t bV = smb + VS_OFF
            + (uint32_t)((rg * 16 + (l & 7) + ((l >> 4) << 3)) * 528
                         + (((l >> 3) & 1) << 4) + grp * 256);
        #pragma unroll
        for (int kc = 0; kc < 4; kc++) {
            uint32_t vb[4];
            ldm4(vb, bV + kc * 32);
            mma16816(oacc[rg * 2 + 0], pa[kc], vb[0], vb[1]);
            mma16816(oacc[rg * 2 + 1], pa[kc], vb[2], vb[3]);
        }
    }
    // ---- kb=1 ----
    {
        float sacc[8][4];
        #pragma unroll
        for (int t = 0; t < 8; t++)
            #pragma unroll
            for (int e = 0; e < 4; e++) sacc[t][e] = 0.f;
        #pragma unroll
        for (int mg = 0; mg < 4; mg++) {
            uint32_t bK = smb + KS_OFF
                + (uint32_t)((grp * 128 + 64 + mg * 16 + (l & 7) + ((l >> 4) << 3)) * 144
                             + (((l >> 3) & 1) << 4));
            #pragma unroll
            for (int kc = 0; kc < 4; kc++) {
                uint32_t kbf[4];
                ldm4(kbf, bK + kc * 32);
                mma16816(sacc[mg * 2 + 0], qa[kc], kbf[0], kbf[1]);
                mma16816(sacc[mg * 2 + 1], qa[kc], kbf[2], kbf[3]);
            }
        }
        #pragma unroll
        for (int t = 0; t < 8; t++) {
            float p0 = __expf((sacc[t][0] - 64.0f) * invs);
            float p1 = __expf((sacc[t][1] - 64.0f) * invs);
            float p2 = __expf((sacc[t][2] - 64.0f) * invs);
            float p3 = __expf((sacc[t][3] - 64.0f) * invs);
            rs_lo += p0 + p1; rs_hi += p2 + p3;
            int j = t >> 1;
            if ((t & 1) == 0) { pa[j][0] = pack2(p0, p1); pa[j][1] = pack2(p2, p3); }
            else              { pa[j][2] = pack2(p0, p1); pa[j][3] = pack2(p2, p3); }
        }
        #pragma unroll
        for (int rg = 0; rg < 4; rg++) {
            uint32_t bV = smb + VS_OFF
                + (uint32_t)((rg * 16 + (l & 7) + ((l >> 4) << 3)) * 528
                             + (((l >> 3) & 1) << 4) + grp * 256 + 128);
            #pragma unroll
            for (int kc = 0; kc < 4; kc++) {
                uint32_t vb[4];
                ldm4(vb, bV + kc * 32);
                mma16816(oacc[rg * 2 + 0], pa[kc], vb[0], vb[1]);
                mma16816(oacc[rg * 2 + 1], pa[kc], vb[2], vb[3]);
            }
        }
    }
    rs_lo += __shfl_xor_sync(0xffffffffu, rs_lo, 1);
    rs_lo += __shfl_xor_sync(0xffffffffu, rs_lo, 2);
    rs_hi += __shfl_xor_sync(0xffffffffu, rs_hi, 1);
    rs_hi += __shfl_xor_sync(0xffffffffu, rs_hi, 2);

    __syncthreads();
    {
        float* Op = (float*)(sm2 + (grp ? KS_OFF : VS_OFF)) + (wh * 32 + l) * 33;
        #pragma unroll
        for (int t = 0; t < 8; t++)
            #pragma unroll
            for (int e = 0; e < 4; e++) Op[t * 4 + e] = oacc[t][e];
        float* Rp = (float*)(sm2 + RS_OFF) + (grp * 256 + wh * 32 + l) * 2;
        Rp[0] = rs_lo; Rp[1] = rs_hi;
    }
    __syncthreads();
    {
        const float* Op = (const float*)(sm2 + (grp ? VS_OFF : KS_OFF)) + (wh * 32 + l) * 33;
        const float* Rp = (const float*)(sm2 + RS_OFF) + ((1 - grp) * 256 + wh * 32 + l) * 2;
        rs_lo += Rp[0]; rs_hi += Rp[1];
        #pragma unroll
        for (int t = 0; t < 8; t++)
            #pragma unroll
            for (int e = 0; e < 4; e++) oacc[t][e] += Op[t * 4 + e];
    }
    float il = 1.0f / rs_lo, ih = 1.0f / rs_hi;
    uint32_t oa[4][4];
    #pragma unroll
    for (int j = 0; j < 4; j++) {
        oa[j][0] = pack2(oacc[2 * j][0] * il, oacc[2 * j][1] * il);
        oa[j][1] = pack2(oacc[2 * j][2] * ih, oacc[2 * j][3] * ih);
        oa[j][2] = pack2(oacc[2 * j + 1][0] * il, oacc[2 * j + 1][1] * il);
        oa[j][3] = pack2(oacc[2 * j + 1][2] * ih, oacc[2 * j + 1][3] * ih);
    }

    // transition: both groups compute full M
    float macc[8][4];
    #pragma unroll
    for (int t = 0; t < 8; t++)
        #pragma unroll
        for (int e = 0; e < 4; e++) macc[t][e] = 0.f;
    #pragma unroll
    for (int sg = 0; sg < 4; sg++) {
        uint32_t bW = smb + WS_OFF
            + (uint32_t)((sg * 16 + (l & 7) + ((l >> 4) << 3)) * 144 + (((l >> 3) & 1) << 4));
        #pragma unroll
        for (int kc = 0; kc < 4; kc++) {
            uint32_t wb[4];
            ldm4(wb, bW + kc * 32);
            mma16816(macc[sg * 2 + 0], oa[kc], wb[0], wb[1]);
            mma16816(macc[sg * 2 + 1], oa[kc], wb[2], wb[3]);
        }
    }
    #pragma unroll
    for (int t = 0; t < 8; t++)
        #pragma unroll
        for (int e = 0; e < 4; e++) {
            float z = macc[t][e];
            macc[t][e] = z * __frcp_rn(1.0f + __expf(-z));
        }

    if (last) {
        // fused final quadratic reduction (replaces k_final; g_M never materialized)
        float tt = 0.f;
        if (grp == 0) {
            float blk[2][8];
            #pragma unroll
            for (int t = 0; t < 8; t++) {
                blk[0][t] = macc[t][0] * macc[t][0] + macc[t][1] * macc[t][1];
                blk[1][t] = macc[t][2] * macc[t][2] + macc[t][3] * macc[t][3];
            }
            #pragma unroll
            for (int o = 1; o <= 2; o++)
                #pragma unroll
                for (int t = 0; t < 8; t++) {
                    blk[0][t] += __shfl_xor_sync(0xffffffffu, blk[0][t], o);
                    blk[1][t] += __shfl_xor_sync(0xffffffffu, blk[1][t], o);
                }
            if ((l & 3) == 0) {
                const float* xb = x + (size_t)b * ND * NA;
                int tb0 = halfsel * 128 + n0 + (l >> 2);
                #pragma unroll
                for (int rsel = 0; rsel < 2; rsel++) {
                    int tokb = tb0 + rsel * 8;
                    float s11 = blk[rsel][0], s12 = blk[rsel][1];
                    float s21 = blk[rsel][2], s22 = blk[rsel][3];
                    float spp = blk[rsel][4] + blk[rsel][5] + blk[rsel][6] + blk[rsel][7];
                    tt += spp;
                    #pragma unroll
                    for (int kk = 0; kk < 2; kk++) {
                        int k = 2 * tokb + kk;
                        int j = k & 3, col = k >> 2;
                        float q1 = xb[j * NA + col];
                        float q2 = xb[j * NA + 128 + col];
                        tt += s11 * q1 * q1 + (s12 + s21) * q1 * q2 + s22 * q2 * q2;
                    }
                }
            } else tt = 0.f;
        }
        for (int o = 16; o > 0; o >>= 1) tt += __shfl_down_sync(0xffffffffu, tt, o);
        float* sred = (float*)(sm2 + RS_OFF);
        __syncthreads();
        if (l == 0) sred[wid] = tt;
        __syncthreads();
        if (tid == 0) {
            float s = 0.f;
            #pragma unroll
            for (int i = 0; i < 16; i++) s += sred[i];
            atomicAdd(out + b, s);
        }
        return;
    }

    uint32_t ma[4][4];
    #pragma unroll
    for (int j = 0; j < 4; j++) {
        ma[j][0] = pack2(macc[2 * j][0], macc[2 * j][1]);
        ma[j][1] = pack2(macc[2 * j][2], macc[2 * j][3]);
        ma[j][2] = pack2(macc[2 * j + 1][0], macc[2 * j + 1][1]);
        ma[j][3] = pack2(macc[2 * j + 1][2], macc[2 * j + 1][3]);
    }

    // projections: group g handles sg = 2g, 2g+1 (output cols 32g .. 32g+31)
    #pragma unroll 1
    for (int p = 0; p < 3; p++) {
        float zacc[4][4];
        #pragma unroll
        for (int t = 0; t < 4; t++)
            #pragma unroll
            for (int e = 0; e < 4; e++) zacc[t][e] = 0.f;
        #pragma unroll
        for (int sgl = 0; sgl < 2; sgl++) {
            int sg = grp * 2 + sgl;
            uint32_t bW = smb + WS_OFF + (uint32_t)(1 + p) * 9216
                + (uint32_t)((sg * 16 + (l & 7) + ((l >> 4) << 3)) * 144 + (((l >> 3) & 1) << 4));
            #pragma unroll
            for (int kc = 0; kc < 4; kc++) {
                uint32_t wb[4];
                ldm4(wb, bW + kc * 32);
                mma16816(zacc[sgl * 2 + 0], ma[kc], wb[0], wb[1]);
                mma16816(zacc[sgl * 2 + 1], ma[kc], wb[2], wb[3]);
            }
        }
        #pragma unroll
        for (int t = 0; t < 4; t++)
            #pragma unroll
            for (int e = 0; e < 4; e++)
                zacc[t][e] = __frcp_rn(1.0f + __expf(-zacc[t][e]));
        if (p < 2) {
            __half* dstg = (p == 0) ? g_Qh : g_Kh;
            int row = tok0 + n0 + (l >> 2);
            #pragma unroll
            for (int tl = 0; tl < 4; tl++) {
                int tgl = grp * 4 + tl;
                int col = tgl * 8 + (l & 3) * 2;
                *(uint32_t*)(dstg + (size_t)row * NR + col) = pack2(zacc[tl][0], zacc[tl][1]);
                *(uint32_t*)(dstg + (size_t)(row + 8) * NR + col) = pack2(zacc[tl][2], zacc[tl][3]);
            }
        } else {
            int trow = n0 + (l >> 2);
            #pragma unroll
            for (int tl = 0; tl < 4; tl++) {
                int tgl = grp * 4 + tl;
                int col = tgl * 8 + (l & 3) * 2;
                *(__half*)(sm2 + VT_OFF + (col) * 272 + trow * 2)           = __float2half_rn(zacc[tl][0]);
                *(__half*)(sm2 + VT_OFF + (col + 1) * 272 + trow * 2)       = __float2half_rn(zacc[tl][1]);
                *(__half*)(sm2 + VT_OFF + (col) * 272 + (trow + 8) * 2)     = __float2half_rn(zacc[tl][2]);
                *(__half*)(sm2 + VT_OFF + (col + 1) * 272 + (trow + 8) * 2) = __float2half_rn(zacc[tl][3]);
            }
            __syncthreads();
            int r = tid >> 3, seg = tid & 7;
            __half* dst = g_VhT + ((size_t)b * NR + r) * NA + halfsel * 128 + seg * 16;
            #pragma unroll
            for (int u = 0; u < 2; u++)
                *(uint4*)(dst + u * 8) = *(uint4*)(sm2 + VT_OFF + r * 272 + (seg * 16 + u * 8) * 2);
        }
    }
}

extern "C" void kernel_launch(void* const* d_in, const int* in_sizes, int n_in,
                              void* d_out, int out_size) {
    const float* x   = (const float*)d_in[0];
    const float* L   = (const float*)d_in[1];
    const float* Aq  = (const float*)d_in[2];
    const float* Ak  = (const float*)d_in[3];
    const float* Av  = (const float*)d_in[4];
    const float* Aq1 = (const float*)d_in[5];
    const float* Ak1 = (const float*)d_in[6];
    const float* Av1 = (const float*)d_in[7];
    const float* Aq5 = (const float*)d_in[8];
    const float* Ak5 = (const float*)d_in[9];
    const float* Av5 = (const float*)d_in[10];
    const float* Ao  = (const float*)d_in[11];
    const float* Ao1 = (const float*)d_in[12];
    const float* Ao5 = (const float*)d_in[13];
    float* out = (float*)d_out;

    cudaFuncSetAttribute(k_gemmTC, cudaFuncAttributeMaxDynamicSharedMemorySize, GT_SMEM);
    cudaFuncSetAttribute(k_attn2,  cudaFuncAttributeMaxDynamicSharedMemorySize, AT_SMEM);

    k_misc<<<266, 256>>>(L, out, Aq, Ak, Av, Ao, Aq1, Ak1, Av1, Ao1, Aq5, Ak5, Av5, Ao5);
    k_gemmTC<<<256, 256, GT_SMEM>>>(x);

    k_attn2<<<dim3(2, NB), 512, AT_SMEM>>>(0, 4, 0, x, out);
    k_attn2<<<dim3(2, NB), 512, AT_SMEM>>>(4, 4, 0, x, out);
    k_attn2<<<dim3(2, NB), 512, AT_SMEM>>>(8, 1, 1, x, out);
}

// round 17
// speedup vs baseline: 1.4650x; 1.4650x over previous
#include <cuda_runtime.h>
#include <cuda_fp16.h>
#include <math.h>
#include <cstdint>

#define NB 64
#define ND 2048
#define NA 256
#define NR 64
#define NTOK (NB*NA)   // 16384 tokens

// ---------------- device scratch (allocation-free rule) ----------------
__device__ float g_scale[NB];
__device__ __align__(16) float g_M[NB*NA*NR];
__device__ __align__(16) __half g_Qh[(size_t)NTOK*NR];   // token-major [tok][r]
__device__ __align__(16) __half g_Kh[(size_t)NTOK*NR];   // token-major [tok][r]
__device__ __align__(16) __half g_VhT[(size_t)NB*NR*NA]; // r-major [b][r][tok]
__device__ __align__(16) __half g_WH[9*4096];            // 0:Ao 1:Aq1 2:Ak1 3:Av1 4:Ao1 5:Aq5 6:Ak5 7:Av5 8:Ao5
// fp16 hi/lo split W for the layer-1 tensor GEMM
__device__ __align__(16) __half g_Whi[192*ND];
__device__ __align__(16) __half g_Wlo[192*ND];

// ---------------- PTX helpers ----------------
__device__ __forceinline__ uint32_t smem_u32(const void* p) {
    uint32_t a;
    asm("{ .reg .u64 t; cvta.to.shared.u64 t, %1; cvt.u32.u64 %0, t; }" : "=r"(a) : "l"(p));
    return a;
}
__device__ __forceinline__ void cp16(uint32_t d, const void* s) {
    asm volatile("cp.async.cg.shared.global [%0], [%1], 16;" :: "r"(d), "l"(s));
}
__device__ __forceinline__ void ldm4(uint32_t* r, uint32_t a) {
    asm volatile("ldmatrix.sync.aligned.m8n8.x4.shared.b16 {%0,%1,%2,%3}, [%4];"
        : "=r"(r[0]), "=r"(r[1]), "=r"(r[2]), "=r"(r[3]) : "r"(a));
}
__device__ __forceinline__ void mma16816(float* d, const uint32_t* a, uint32_t b0, uint32_t b1) {
    asm volatile("mma.sync.aligned.m16n8k16.row.col.f32.f16.f16.f32 "
        "{%0,%1,%2,%3}, {%4,%5,%6,%7}, {%8,%9}, {%0,%1,%2,%3};"
        : "+f"(d[0]), "+f"(d[1]), "+f"(d[2]), "+f"(d[3])
        : "r"(a[0]), "r"(a[1]), "r"(a[2]), "r"(a[3]), "r"(b0), "r"(b1));
}
__device__ __forceinline__ uint32_t pack2(float a, float b) {
    __half2 h = __floats2half2_rn(a, b);
    return *(uint32_t*)&h;
}

// ---------------- merged prep: small weights fp16, per-batch scale, W hi/lo split ----
__global__ void __launch_bounds__(256) k_misc(const float* __restrict__ L,
                       const float* __restrict__ Aq, const float* __restrict__ Ak,
                       const float* __restrict__ Av,
                       const float* A0, const float* A1, const float* A2,
                       const float* A3, const float* A4, const float* A5,
                       const float* A6, const float* A7, const float* A8) {
    int blk = blockIdx.x;
    int tid = threadIdx.x;
    if (blk < 9) {
        const float* ptrs[9] = {A0, A1, A2, A3, A4, A5, A6, A7, A8};
        const float* src = ptrs[blk];
        __half* dst = g_WH + blk * 4096;
        for (int i = tid; i < 4096; i += 256) dst[i] = __float2half_rn(src[i]);
        return;
    }
    if (blk < 73) {
        int b = blk - 9;
        float c = (L[b * 2 * NA + tid] >= 1.0f) ? 1.0f : 0.0f;
        __shared__ float red[8];
        for (int o = 16; o > 0; o >>= 1) c += __shfl_down_sync(0xffffffffu, c, o);
        if ((tid & 31) == 0) red[tid >> 5] = c;
        __syncthreads();
        if (tid == 0) {
            float t = 0.f;
            #pragma unroll
            for (int i = 0; i < 8; i++) t += red[i];
            g_scale[b] = sqrtf(t + 1.0f);
        }
        return;
    }
    // W hi/lo split: r = blk - 73 in 0..191
    int r = blk - 73;
    const float* src = (r < 64)  ? Aq + (size_t)r * ND
                     : (r < 128) ? Ak + (size_t)(r - 64) * ND
                                 : Av + (size_t)(r - 128) * ND;
    #pragma unroll
    for (int i = 0; i < 8; i++) {
        int k = tid + (i << 8);
        float a = src[k];
        __half h = __float2half_rn(a);
        __half l = __float2half_rn(a - __half2float(h));
        g_Whi[(size_t)r * ND + k] = h;
        g_Wlo[(size_t)r * ND + k] = l;
    }
}

// ---------------- fused layer-1 QKV GEMM with in-kernel x conversion (R9, locked) ----
#define ROWB    80
#define XH_ROW  384
#define XL_ROW  448
#define XF_OFF  40960u
#define XF_PITCH 272u
#define STAGE   49664u
#define GT_SMEM (2 * 49664)
__global__ void __launch_bounds__(256, 2) k_gemmTC(const float* __restrict__ x) {
    extern __shared__ __align__(16) char sm[];
    uint32_t smb = smem_u32(sm);
    int tid = threadIdx.x;
    int tok0 = blockIdx.x << 6;
    int bb_idx = tok0 >> 8;
    int n0 = tok0 & 255;
    int wid = tid >> 5, l = tid & 31;
    int mbase = (wid >> 1) * 48;
    int nbase = (wid & 1) << 5;

    float acc[3][4][4];
    #pragma unroll
    for (int mi = 0; mi < 3; mi++)
        #pragma unroll
        for (int nt = 0; nt < 4; nt++)
            #pragma unroll
            for (int e = 0; e < 4; e++) acc[mi][nt][e] = 0.f;

    uint32_t aOff = (uint32_t)((mbase + (l & 15)) * ROWB + ((l >> 4) << 4));
    uint32_t bOff = (uint32_t)((XH_ROW + nbase + (l & 7) + ((l >> 4) << 3)) * ROWB
                               + (((l >> 3) & 1) << 4));

    const float* xb = x + ((size_t)bb_idx * ND) * NA + n0;

    auto load_stage = [&](int c, int buf) {
        uint32_t bb = smb + (uint32_t)buf * STAGE;
        int k0 = c << 5;
        #pragma unroll
        for (int i = 0; i < 6; i++) {
            int s = tid + (i << 8);
            int row = s >> 2, u = s & 3;
            const __half* src = (row < 192)
                ? g_Whi + (size_t)row * ND + k0 + (u << 3)
                : g_Wlo + (size_t)(row - 192) * ND + k0 + (u << 3);
            cp16(bb + (uint32_t)(row * ROWB + (u << 4)), src);
        }
        #pragma unroll
        for (int i = 0; i < 2; i++) {
            int s = tid + (i << 8);
            int krow = s >> 4, u = s & 15;
            cp16(bb + XF_OFF + (uint32_t)(krow * XF_PITCH + (u << 4)),
                 xb + (size_t)(k0 + krow) * NA + (u << 2));
        }
        asm volatile("cp.async.commit_group;" ::: "memory");
    };

    int tq0 = tid & 15;
    int kq = (tid >> 4) << 1;

    load_stage(0, 0);
    for (int c = 0; c < 64; c++) {
        if (c < 63) {
            load_stage(c + 1, (c + 1) & 1);
            asm volatile("cp.async.wait_group 1;" ::: "memory");
        } else {
            asm volatile("cp.async.wait_group 0;" ::: "memory");
        }
        __syncthreads();
        char* bp = sm + (size_t)(c & 1) * STAGE;
        #pragma unroll
        for (int i = 0; i < 4; i++) {
            int tok = tq0 + (i << 4);
            float f0 = *(const float*)(bp + XF_OFF + kq * XF_PITCH + tok * 4);
            float f1 = *(const float*)(bp + XF_OFF + (kq + 1) * XF_PITCH + tok * 4);
            __half h0 = __float2half_rn(f0), h1 = __float2half_rn(f1);
            __half2 hh; hh.x = h0; hh.y = h1;
            *(uint32_t*)(bp + (XH_ROW + tok) * ROWB + kq * 2) = *(uint32_t*)&hh;
            *(uint32_t*)(bp + (XL_ROW + tok) * ROWB + kq * 2)
                = pack2(f0 - __half2float(h0), f1 - __half2float(h1));
        }
        __syncthreads();
        uint32_t bbu = smb + (uint32_t)(c & 1) * STAGE;
        uint32_t Ah = bbu + aOff;
        uint32_t Al = Ah + 192u * ROWB;
        uint32_t Bh = bbu + bOff;
        uint32_t Bl = Bh + 64u * ROWB;
        #pragma unroll
        for (int ks = 0; ks < 2; ks++) {
            uint32_t ko = (uint32_t)(ks << 5);
            uint32_t ah[3][4], al[3][4], bh[2][4], bl[2][4];
            #pragma unroll
            for (int mi = 0; mi < 3; mi++) {
                ldm4(ah[mi], Ah + (uint32_t)(mi * 16 * ROWB) + ko);
                ldm4(al[mi], Al + (uint32_t)(mi * 16 * ROWB) + ko);
            }
            #pragma unroll
            for (int nj = 0; nj < 2; nj++) {
                ldm4(bh[nj], Bh + (uint32_t)(nj * 16 * ROWB) + ko);
                ldm4(bl[nj], Bl + (uint32_t)(nj * 16 * ROWB) + ko);
            }
            #pragma unroll
            for (int mi = 0; mi < 3; mi++)
                #pragma unroll
                for (int nj = 0; nj < 2; nj++)
                    #pragma unroll
                    for (int h = 0; h < 2; h++) {
                        float* d = acc[mi][nj * 2 + h];
                        mma16816(d, ah[mi], bh[nj][2 * h], bh[nj][2 * h + 1]);
                        mma16816(d, ah[mi], bl[nj][2 * h], bl[nj][2 * h + 1]);
                        mma16816(d, al[mi], bh[nj][2 * h], bh[nj][2 * h + 1]);
                    }
        }
        __syncthreads();
    }

    float* S = (float*)sm;
    int lr = l >> 2, lc = (l & 3) << 1;
    #pragma unroll
    for (int mi = 0; mi < 3; mi++)
        #pragma unroll
        for (int nj = 0; nj < 2; nj++)
            #pragma unroll
            for (int h = 0; h < 2; h++) {
                int m = mbase + mi * 16 + lr;
                int n = nbase + nj * 16 + h * 8 + lc;
                float* d = acc[mi][nj * 2 + h];
                S[n * 196 + m]           = __frcp_rn(1.0f + __expf(-d[0]));
                S[(n + 1) * 196 + m]     = __frcp_rn(1.0f + __expf(-d[1]));
                S[n * 196 + m + 8]       = __frcp_rn(1.0f + __expf(-d[2]));
                S[(n + 1) * 196 + m + 8] = __frcp_rn(1.0f + __expf(-d[3]));
            }
    __syncthreads();
    #pragma unroll
    for (int i = 0; i < 4; i++) {
        int e = tid + (i << 8);
        int tok = e >> 4, q = e & 15;
        float4 vq = *(const float4*)(S + tok * 196 + (q << 2));
        float4 vk = *(const float4*)(S + tok * 196 + 64 + (q << 2));
        uint2 pq, pk;
        pq.x = pack2(vq.x, vq.y); pq.y = pack2(vq.z, vq.w);
        pk.x = pack2(vk.x, vk.y); pk.y = pack2(vk.z, vk.w);
        *(uint2*)(g_Qh + (size_t)(tok0 + tok) * NR + (q << 2)) = pq;
        *(uint2*)(g_Kh + (size_t)(tok0 + tok) * NR + (q << 2)) = pk;
    }
    {
        int r = tid >> 2, seg = tid & 3;
        __half* dst = g_VhT + ((size_t)bb_idx * NR + r) * NA + n0 + seg * 16;
        #pragma unroll
        for (int u = 0; u < 2; u++) {
            uint4 w;
            uint32_t* wp = (uint32_t*)&w;
            #pragma unroll
            for (int j2 = 0; j2 < 4; j2++) {
                int tk = seg * 16 + u * 8 + j2 * 2;
                wp[j2] = pack2(S[tk * 196 + 128 + r], S[(tk + 1) * 196 + 128 + r]);
            }
            *(uint4*)(dst + u * 8) = w;
        }
    }
}

// ---------------- FUSED attention + transition + QKV projections, 512 threads (R15) ---
#define QS_OFF 0u
#define KS_OFF 18432u
#define VS_OFF 55296u
#define WS_OFF 89088u
#define RS_OFF 125952u
#define VT_OFF 0u
#define AT_SMEM 130048
__global__ void __launch_bounds__(512, 1) k_attn2(int wbase, int nw, int last) {
    extern __shared__ __align__(16) char sm2[];
    uint32_t smb = smem_u32(sm2);
    int tid = threadIdx.x, wid = tid >> 5, l = tid & 31;
    int wh = wid & 7, grp = wid >> 3;
    int b = blockIdx.y;
    int halfsel = blockIdx.x;
    int tok0 = b * NA + halfsel * 128;

    // group A loads: Q + K
    #pragma unroll
    for (int i = 0; i < 2; i++) {
        int e = tid + (i << 9); int row = e >> 3, u = e & 7;
        cp16(smb + QS_OFF + row * 144 + u * 16, g_Qh + (size_t)(tok0 + row) * NR + u * 8);
    }
    #pragma unroll
    for (int i = 0; i < 4; i++) {
        int e = tid + (i << 9); int row = e >> 3, u = e & 7;
        cp16(smb + KS_OFF + row * 144 + u * 16, g_Kh + (size_t)(b * NA + row) * NR + u * 8);
    }
    asm volatile("cp.async.commit_group;" ::: "memory");
    // group B loads: V + W
    #pragma unroll
    for (int i = 0; i < 4; i++) {
        int e = tid + (i << 9); int r = e >> 5, u = e & 31;
        cp16(smb + VS_OFF + r * 528 + u * 16, g_VhT + ((size_t)b * NR + r) * NA + u * 8);
    }
    for (int wi = 0; wi < nw; wi++) {
        int row = tid >> 3, u = tid & 7;
        cp16(smb + WS_OFF + (uint32_t)wi * 9216 + row * 144 + u * 16,
             g_WH + (size_t)(wbase + wi) * 4096 + row * 64 + u * 8);
    }
    asm volatile("cp.async.commit_group;" ::: "memory");
    float invs = 1.0f / g_scale[b];
    asm volatile("cp.async.wait_group 1;" ::: "memory");
    __syncthreads();

    int n0 = wh << 4;
    uint32_t qa[4][4];
    uint32_t aQ = smb + QS_OFF + (uint32_t)((n0 + (l & 15)) * 144 + ((l >> 4) << 4));
    #pragma unroll
    for (int kc = 0; kc < 4; kc++) ldm4(qa[kc], aQ + kc * 32);

    float oacc[8][4];
    #pragma unroll
    for (int t = 0; t < 8; t++)
        #pragma unroll
        for (int e = 0; e < 4; e++) oacc[t][e] = 0.f;
    float rs_lo = 0.f, rs_hi = 0.f;

    uint32_t pa[4][4];
    // ---- kb=0: QK + exp (runs while V/W land) ----
    {
        float sacc[8][4];
        #pragma unroll
        for (int t = 0; t < 8; t++)
            #pragma unroll
            for (int e = 0; e < 4; e++) sacc[t][e] = 0.f;
        #pragma unroll
        for (int mg = 0; mg < 4; mg++) {
            uint32_t bK = smb + KS_OFF
                + (uint32_t)((grp * 128 + mg * 16 + (l & 7) + ((l >> 4) << 3)) * 144
                             + (((l >> 3) & 1) << 4));
            #pragma unroll
            for (int kc = 0; kc < 4; kc++) {
                uint32_t kbf[4];
                ldm4(kbf, bK + kc * 32);
                mma16816(sacc[mg * 2 + 0], qa[kc], kbf[0], kbf[1]);
                mma16816(sacc[mg * 2 + 1], qa[kc], kbf[2], kbf[3]);
            }
        }
        #pragma unroll
        for (int t = 0; t < 8; t++) {
            float p0 = __expf((sacc[t][0] - 64.0f) * invs);
            float p1 = __expf((sacc[t][1] - 64.0f) * invs);
            float p2 = __expf((sacc[t][2] - 64.0f) * invs);
            float p3 = __expf((sacc[t][3] - 64.0f) * invs);
            rs_lo += p0 + p1; rs_hi += p2 + p3;
            int j = t >> 1;
            if ((t & 1) == 0) { pa[j][0] = pack2(p0, p1); pa[j][1] = pack2(p2, p3); }
            else              { pa[j][2] = pack2(p0, p1); pa[j][3] = pack2(p2, p3); }
        }
    }
    asm volatile("cp.async.wait_group 0;" ::: "memory");
    __syncthreads();
    #pragma unroll
    for (int rg = 0; rg < 4; rg++) {
        uint32_t bV = smb + VS_OFF
            + (uint32_t)((rg * 16 + (l & 7) + ((l >> 4) << 3)) * 528
                         + (((l >> 3) & 1) << 4) + grp * 256);
        #pragma unroll
        for (int kc = 0; kc < 4; kc++) {
            uint32_t vb[4];
            ldm4(vb, bV + kc * 32);
            mma16816(oacc[rg * 2 + 0], pa[kc], vb[0], vb[1]);
            mma16816(oacc[rg * 2 + 1], pa[kc], vb[2], vb[3]);
        }
    }
    // ---- kb=1 ----
    {
        float sacc[8][4];
        #pragma unroll
        for (int t = 0; t < 8; t++)
            #pragma unroll
            for (int e = 0; e < 4; e++) sacc[t][e] = 0.f;
        #pragma unroll
        for (int mg = 0; mg < 4; mg++) {
            uint32_t bK = smb + KS_OFF
                + (uint32_t)((grp * 128 + 64 + mg * 16 + (l & 7) + ((l >> 4) << 3)) * 144
                             + (((l >> 3) & 1) << 4));
            #pragma unroll
            for (int kc = 0; kc < 4; kc++) {
                uint32_t kbf[4];
                ldm4(kbf, bK + kc * 32);
                mma16816(sacc[mg * 2 + 0], qa[kc], kbf[0], kbf[1]);
                mma16816(sacc[mg * 2 + 1], qa[kc], kbf[2], kbf[3]);
            }
        }
        #pragma unroll
        for (int t = 0; t < 8; t++) {
            float p0 = __expf((sacc[t][0] - 64.0f) * invs);
            float p1 = __expf((sacc[t][1] - 64.0f) * invs);
            float p2 = __expf((sacc[t][2] - 64.0f) * invs);
            float p3 = __expf((sacc[t][3] - 64.0f) * invs);
            rs_lo += p0 + p1; rs_hi += p2 + p3;
            int j = t >> 1;
            if ((t & 1) == 0) { pa[j][0] = pack2(p0, p1); pa[j][1] = pack2(p2, p3); }
            else              { pa[j][2] = pack2(p0, p1); pa[j][3] = pack2(p2, p3); }
        }
        #pragma unroll
        for (int rg = 0; rg < 4; rg++) {
            uint32_t bV = smb + VS_OFF
                + (uint32_t)((rg * 16 + (l & 7) + ((l >> 4) << 3)) * 528
                             + (((l >> 3) & 1) << 4) + grp * 256 + 128);
            #pragma unroll
            for (int kc = 0; kc < 4; kc++) {
                uint32_t vb[4];
                ldm4(vb, bV + kc * 32);
                mma16816(oacc[rg * 2 + 0], pa[kc], vb[0], vb[1]);
                mma16816(oacc[rg * 2 + 1], pa[kc], vb[2], vb[3]);
            }
        }
    }
    rs_lo += __shfl_xor_sync(0xffffffffu, rs_lo, 1);
    rs_lo += __shfl_xor_sync(0xffffffffu, rs_lo, 2);
    rs_hi += __shfl_xor_sync(0xffffffffu, rs_hi, 1);
    rs_hi += __shfl_xor_sync(0xffffffffu, rs_hi, 2);

    __syncthreads();    // K & V reads done; overlay partial buffers
    {
        float* Op = (float*)(sm2 + (grp ? KS_OFF : VS_OFF)) + (wh * 32 + l) * 33;
        #pragma unroll
        for (int t = 0; t < 8; t++)
            #pragma unroll
            for (int e = 0; e < 4; e++) Op[t * 4 + e] = oacc[t][e];
        float* Rp = (float*)(sm2 + RS_OFF) + (grp * 256 + wh * 32 + l) * 2;
        Rp[0] = rs_lo; Rp[1] = rs_hi;
    }
    __syncthreads();
    {
        const float* Op = (const float*)(sm2 + (grp ? VS_OFF : KS_OFF)) + (wh * 32 + l) * 33;
        const float* Rp = (const float*)(sm2 + RS_OFF) + ((1 - grp) * 256 + wh * 32 + l) * 2;
        rs_lo += Rp[0]; rs_hi += Rp[1];
        #pragma unroll
        for (int t = 0; t < 8; t++)
            #pragma unroll
            for (int e = 0; e < 4; e++) oacc[t][e] += Op[t * 4 + e];
    }
    float il = 1.0f / rs_lo, ih = 1.0f / rs_hi;
    uint32_t oa[4][4];
    #pragma unroll
    for (int j = 0; j < 4; j++) {
        oa[j][0] = pack2(oacc[2 * j][0] * il, oacc[2 * j][1] * il);
        oa[j][1] = pack2(oacc[2 * j][2] * ih, oacc[2 * j][3] * ih);
        oa[j][2] = pack2(oacc[2 * j + 1][0] * il, oacc[2 * j + 1][1] * il);
        oa[j][3] = pack2(oacc[2 * j + 1][2] * ih, oacc[2 * j + 1][3] * ih);
    }

    // transition: both groups compute full M
    float macc[8][4];
    #pragma unroll
    for (int t = 0; t < 8; t++)
        #pragma unroll
        for (int e = 0; e < 4; e++) macc[t][e] = 0.f;
    #pragma unroll
    for (int sg = 0; sg < 4; sg++) {
        uint32_t bW = smb + WS_OFF
            + (uint32_t)((sg * 16 + (l & 7) + ((l >> 4) << 3)) * 144 + (((l >> 3) & 1) << 4));
        #pragma unroll
        for (int kc = 0; kc < 4; kc++) {
            uint32_t wb[4];
            ldm4(wb, bW + kc * 32);
            mma16816(macc[sg * 2 + 0], oa[kc], wb[0], wb[1]);
            mma16816(macc[sg * 2 + 1], oa[kc], wb[2], wb[3]);
        }
    }
    #pragma unroll
    for (int t = 0; t < 8; t++)
        #pragma unroll
        for (int e = 0; e < 4; e++) {
            float z = macc[t][e];
            macc[t][e] = z * __frcp_rn(1.0f + __expf(-z));
        }

    if (last) {
        // split M stores: group g stores t = 4g .. 4g+3
        int row = tok0 + n0 + (l >> 2);
        #pragma unroll
        for (int tl = 0; tl < 4; tl++) {
            int t = grp * 4 + tl;
            int col = t * 8 + (l & 3) * 2;
            float2 v0 = make_float2(macc[t][0], macc[t][1]);
            float2 v1 = make_float2(macc[t][2], macc[t][3]);
            *(float2*)(g_M + (size_t)row * NR + col) = v0;
            *(float2*)(g_M + (size_t)(row + 8) * NR + col) = v1;
        }
        return;
    }

    uint32_t ma[4][4];
    #pragma unroll
    for (int j = 0; j < 4; j++) {
        ma[j][0] = pack2(macc[2 * j][0], macc[2 * j][1]);
        ma[j][1] = pack2(macc[2 * j][2], macc[2 * j][3]);
        ma[j][2] = pack2(macc[2 * j + 1][0], macc[2 * j + 1][1]);
        ma[j][3] = pack2(macc[2 * j + 1][2], macc[2 * j + 1][3]);
    }

    // projections: group g handles sg = 2g, 2g+1 (output cols 32g .. 32g+31)
    #pragma unroll 1
    for (int p = 0; p < 3; p++) {
        float zacc[4][4];
        #pragma unroll
        for (int t = 0; t < 4; t++)
            #pragma unroll
            for (int e = 0; e < 4; e++) zacc[t][e] = 0.f;
        #pragma unroll
        for (int sgl = 0; sgl < 2; sgl++) {
            int sg = grp * 2 + sgl;
            uint32_t bW = smb + WS_OFF + (uint32_t)(1 + p) * 9216
                + (uint32_t)((sg * 16 + (l & 7) + ((l >> 4) << 3)) * 144 + (((l >> 3) & 1) << 4));
            #pragma unroll
            for (int kc = 0; kc < 4; kc++) {
                uint32_t wb[4];
                ldm4(wb, bW + kc * 32);
                mma16816(zacc[sgl * 2 + 0], ma[kc], wb[0], wb[1]);
                mma16816(zacc[sgl * 2 + 1], ma[kc], wb[2], wb[3]);
            }
        }
        #pragma unroll
        for (int t = 0; t < 4; t++)
            #pragma unroll
            for (int e = 0; e < 4; e++)
                zacc[t][e] = __frcp_rn(1.0f + __expf(-zacc[t][e]));
        if (p < 2) {
            __half* dstg = (p == 0) ? g_Qh : g_Kh;
            int row = tok0 + n0 + (l >> 2);
            #pragma unroll
            for (int tl = 0; tl < 4; tl++) {
                int tgl = grp * 4 + tl;
                int col = tgl * 8 + (l & 3) * 2;
                *(uint32_t*)(dstg + (size_t)row * NR + col) = pack2(zacc[tl][0], zacc[tl][1]);
                *(uint32_t*)(dstg + (size_t)(row + 8) * NR + col) = pack2(zacc[tl][2], zacc[tl][3]);
            }
        } else {
            int trow = n0 + (l >> 2);
            #pragma unroll
            for (int tl = 0; tl < 4; tl++) {
                int tgl = grp * 4 + tl;
                int col = tgl * 8 + (l & 3) * 2;
                *(__half*)(sm2 + VT_OFF + (col) * 272 + trow * 2)           = __float2half_rn(zacc[tl][0]);
                *(__half*)(sm2 + VT_OFF + (col + 1) * 272 + trow * 2)       = __float2half_rn(zacc[tl][1]);
                *(__half*)(sm2 + VT_OFF + (col) * 272 + (trow + 8) * 2)     = __float2half_rn(zacc[tl][2]);
                *(__half*)(sm2 + VT_OFF + (col + 1) * 272 + (trow + 8) * 2) = __float2half_rn(zacc[tl][3]);
            }
            __syncthreads();
            int r = tid >> 3, seg = tid & 7;
            __half* dst = g_VhT + ((size_t)b * NR + r) * NA + halfsel * 128 + seg * 16;
            #pragma unroll
            for (int u = 0; u < 2; u++)
                *(uint4*)(dst + u * 8) = *(uint4*)(sm2 + VT_OFF + r * 272 + (seg * 16 + u * 8) * 2);
        }
    }
}

// ---------------- final quadratic reduction ----------------
__global__ void k_final(const float* __restrict__ x, float* __restrict__ out) {
    int b = blockIdx.x;
    int n = threadIdx.x;
    const float* mr = g_M + ((size_t)b * NA + n) * NR;
    float s11 = 0.f, s12 = 0.f, s21 = 0.f, s22 = 0.f, spp = 0.f;
    #pragma unroll
    for (int i = 0; i < 8; i++) {
        float a;
        a = mr[i];      s11 += a * a;
        a = mr[8 + i];  s12 += a * a;
        a = mr[16 + i]; s21 += a * a;
        a = mr[24 + i]; s22 += a * a;
    }
    #pragma unroll
    for (int i = 32; i < 64; i++) { float a = mr[i]; spp += a * a; }

    float t = spp;
    const float* xb = x + (size_t)b * ND * NA;
    #pragma unroll
    for (int kk = 0; kk < 2; kk++) {
        int k = 2 * n + kk;
        int j = k & 3;
        int col = k >> 2;
        float q1 = xb[j * NA + col];
        float q2 = xb[j * NA + 128 + col];
        t += s11 * q1 * q1 + (s12 + s21) * q1 * q2 + s22 * q2 * q2;
    }
    __shared__ float red[8];
    for (int o = 16; o > 0; o >>= 1) t += __shfl_down_sync(0xffffffffu, t, o);
    if ((n & 31) == 0) red[n >> 5] = t;
    __syncthreads();
    if (n == 0) {
        float s = 0.f;
        #pragma unroll
        for (int i = 0; i < 8; i++) s += red[i];
        out[b] = s;
    }
}

extern "C" void kernel_launch(void* const* d_in, const int* in_sizes, int n_in,
                              void* d_out, int out_size) {
    const float* x   = (const float*)d_in[0];
    const float* L   = (const float*)d_in[1];
    const float* Aq  = (const float*)d_in[2];
    const float* Ak  = (const float*)d_in[3];
    const float* Av  = (const float*)d_in[4];
    const float* Aq1 = (const float*)d_in[5];
    const float* Ak1 = (const float*)d_in[6];
    const float* Av1 = (const float*)d_in[7];
    const float* Aq5 = (const float*)d_in[8];
    const float* Ak5 = (const float*)d_in[9];
    const float* Av5 = (const float*)d_in[10];
    const float* Ao  = (const float*)d_in[11];
    const float* Ao1 = (const float*)d_in[12];
    const float* Ao5 = (const float*)d_in[13];
    float* out = (float*)d_out;

    cudaFuncSetAttribute(k_gemmTC, cudaFuncAttributeMaxDynamicSharedMemorySize, GT_SMEM);
    cudaFuncSetAttribute(k_attn2,  cudaFuncAttributeMaxDynamicSharedMemorySize, AT_SMEM);

    k_misc<<<265, 256>>>(L, Aq, Ak, Av, Ao, Aq1, Ak1, Av1, Ao1, Aq5, Ak5, Av5, Ao5);
    k_gemmTC<<<256, 256, GT_SMEM>>>(x);

    k_attn2<<<dim3(2, NB), 512, AT_SMEM>>>(0, 4, 0);
    k_attn2<<<dim3(2, NB), 512, AT_SMEM>>>(4, 4, 0);
    k_attn2<<<dim3(2, NB), 512, AT_SMEM>>>(8, 1, 1);

    k_final<<<NB, 256>>>(x, out);
}